// round 3
// baseline (speedup 1.0000x reference)
#include <cuda_runtime.h>
#include <math.h>

#define NTOK 512
#define NH   12
#define NCH  16
#define NPQ  4
#define NPV  8
#define NCS  384
#define NCZ  128
#define NHC  192
#define NOUTD 2112
#define NNN  (NTOK*NTOK)

// ---------------- scratch ----------------------------------------------------
__device__ float g_qraw[NTOK*NHC];               // s@Wq   [i][h*16+c]
__device__ float g_kvraw[NTOK*2*NHC];            // s@Wkv  [i][h*32+c]
__device__ float g_qpraw[NTOK*NH*NPQ*3];         // raw q point proj
__device__ float g_kvpraw[NTOK*NH*(NPQ+NPV)*3];  // raw kv point proj
__device__ float g_qaug[NTOK*NH*32];             // augmented Q' [i][h][32]
__device__ float g_kaugT[NH*32*NTOK];            // augmented K'^T [h][d][j]
__device__ float g_vcat[NH*NTOK*40];             // [h][j][40] = v(16)|vpts(24)
__device__ float g_bpair[NNN*NH];                // 0.577*(z@Wb+bb)  [(i*512+j)][h]
__device__ float g_qk[NH*NNN];                   // Q'.K' logit part [h][i][j]
__device__ float g_attn[NH*NNN];                 // softmaxed attention [h][i][j]
__device__ float g_cat[NTOK*NOUTD];              // concat features

// ---------------- Kernel 1: projections from s ------------------------------
__global__ void proj_kernel(const float* __restrict__ s,
                            const float* __restrict__ Wq,   const float* __restrict__ bq,
                            const float* __restrict__ Wkv,  const float* __restrict__ bkv,
                            const float* __restrict__ Wqp,  const float* __restrict__ bqp,
                            const float* __restrict__ Wkvp, const float* __restrict__ bkvp)
{
    __shared__ float s_s[16][384];
    const int tid = threadIdx.x;
    const int i0  = blockIdx.x * 16;
    for (int idx = tid; idx < 16*384; idx += 256)
        s_s[idx/384][idx%384] = s[i0*384 + idx];
    __syncthreads();

    const float* W; const float* bias; float* out; int Nc; int ct;
    const int by = blockIdx.y;
    if      (by < 3)  { W=Wq;   bias=bq;   out=g_qraw;   Nc=192; ct=by;    }
    else if (by < 9)  { W=Wkv;  bias=bkv;  out=g_kvraw;  Nc=384; ct=by-3;  }
    else if (by < 12) { W=Wqp;  bias=bqp;  out=g_qpraw;  Nc=144; ct=by-9;  }
    else              { W=Wkvp; bias=bkvp; out=g_kvpraw; Nc=432; ct=by-12; }

    const int col = ct*64 + (tid & 63);
    if (col >= Nc) return;
    const int t0 = (tid >> 6) * 4;

    float a0=0.f, a1=0.f, a2=0.f, a3=0.f;
    #pragma unroll 4
    for (int k = 0; k < 384; k += 4) {
        float w0 = W[(k+0)*Nc + col];
        float w1 = W[(k+1)*Nc + col];
        float w2 = W[(k+2)*Nc + col];
        float w3 = W[(k+3)*Nc + col];
        float4 v;
        v = *(const float4*)&s_s[t0+0][k]; a0 += v.x*w0 + v.y*w1 + v.z*w2 + v.w*w3;
        v = *(const float4*)&s_s[t0+1][k]; a1 += v.x*w0 + v.y*w1 + v.z*w2 + v.w*w3;
        v = *(const float4*)&s_s[t0+2][k]; a2 += v.x*w0 + v.y*w1 + v.z*w2 + v.w*w3;
        v = *(const float4*)&s_s[t0+3][k]; a3 += v.x*w0 + v.y*w1 + v.z*w2 + v.w*w3;
    }
    const float bv = bias[col];
    out[(i0+t0+0)*Nc + col] = a0 + bv;
    out[(i0+t0+1)*Nc + col] = a1 + bv;
    out[(i0+t0+2)*Nc + col] = a2 + bv;
    out[(i0+t0+3)*Nc + col] = a3 + bv;
}

// ---------------- Kernel 2: rotate points, build Q'/K'^T/Vcat ---------------
__global__ void prep_kernel(const float* __restrict__ rot, const float* __restrict__ trans,
                            const float* __restrict__ hwts)
{
    __shared__ float qpts_s[144];
    __shared__ float kpts_s[144];
    __shared__ float vpts_s[288];
    __shared__ float shw[NH];
    const int i = blockIdx.x;
    const int tid = threadIdx.x;

    if (tid < NH)
        shw[tid] = log1pf(__expf(hwts[tid])) * 0.1360827635f;  // softplus * sqrt(1/54)

    if (tid < 192) {
        const int m = tid;
        const float* R = rot + i*9;
        const float tx = trans[i*3+0], ty = trans[i*3+1], tz = trans[i*3+2];
        float x, y, zc; float* dst;
        if (m < 48) {
            const float* src = g_qpraw + i*144;
            x = src[m]; y = src[48+m]; zc = src[96+m];
            dst = qpts_s + m*3;
        } else {
            const int mm = m - 48;
            const float* src = g_kvpraw + i*432;
            x = src[mm]; y = src[144+mm]; zc = src[288+mm];
            const int h = mm / 12, pp = mm % 12;
            if (pp < 4) dst = kpts_s + (h*4+pp)*3;
            else        dst = vpts_s + (h*8 + pp-4)*3;
        }
        dst[0] = R[0]*x + R[1]*y + R[2]*zc + tx;
        dst[1] = R[3]*x + R[4]*y + R[5]*zc + ty;
        dst[2] = R[6]*x + R[7]*y + R[8]*zc + tz;
    }
    __syncthreads();

    for (int idx = tid; idx < 384; idx += 256) {
        const int h = idx >> 5, d = idx & 31;
        const float hw = shw[h];
        float qv, kv;
        if (d < 16) {
            qv = 0.1443375673f * g_qraw[i*NHC + h*16 + d];
            kv = g_kvraw[i*384 + h*32 + d];
        } else if (d < 28) {
            qv = hw * qpts_s[h*12 + d-16];
            kv = kpts_s[h*12 + d-16];
        } else if (d == 28) {
            float qn = 0.f;
            #pragma unroll
            for (int e = 0; e < 12; e++) { const float t = qpts_s[h*12+e]; qn += t*t; }
            qv = -0.5f * hw * qn;
            kv = 1.0f;
        } else if (d == 29) {
            qv = 1.0f;
            float kn = 0.f;
            #pragma unroll
            for (int e = 0; e < 12; e++) { const float t = kpts_s[h*12+e]; kn += t*t; }
            kv = -0.5f * hw * kn;
        } else { qv = 0.f; kv = 0.f; }
        g_qaug[(i*NH + h)*32 + d] = qv;
        g_kaugT[(h*32 + d)*NTOK + i] = kv;
    }

    for (int idx = tid; idx < 480; idx += 256) {
        const int h = idx / 40, d = idx % 40;
        const float v = (d < 16) ? g_kvraw[i*384 + h*32 + 16 + d]
                                 : vpts_s[h*24 + d-16];
        g_vcat[(h*NTOK + i)*40 + d] = v;
    }
}

// ---------------- Kernel 3: bpair = 0.577*(z@Wb + bb), streaming ------------
// grid 4096 (64 rows each), block 256. Coalesced float4 z reads.
__global__ void __launch_bounds__(256, 6)
bpair_kernel(const float* __restrict__ z, const float* __restrict__ Wb,
             const float* __restrict__ bb)
{
    __shared__ float wbT[NH][128];
    __shared__ float part[256*NH];
    const int tid = threadIdx.x;
    const int row0 = blockIdx.x * 64;

    for (int idx = tid; idx < NH*128; idx += 256) {
        const int h = idx >> 7, c = idx & 127;
        wbT[h][c] = Wb[c*NH + h];
    }
    __syncthreads();

    const int r = tid >> 2, q = tid & 3;
    const float4* zp = (const float4*)z + (size_t)(row0 + r)*32;

    float4 zv[8];
    #pragma unroll
    for (int it = 0; it < 8; it++) zv[it] = zp[it*4 + q];

    float acc[NH];
    #pragma unroll
    for (int h = 0; h < NH; h++) acc[h] = 0.f;

    #pragma unroll
    for (int it = 0; it < 8; it++) {
        const int cbase = (it*4 + q) * 4;
        #pragma unroll
        for (int h = 0; h < NH; h++) {
            const float4 wv = *(const float4*)&wbT[h][cbase];
            acc[h] += zv[it].x*wv.x + zv[it].y*wv.y + zv[it].z*wv.z + zv[it].w*wv.w;
        }
    }
    #pragma unroll
    for (int h = 0; h < NH; h++) part[tid*NH + h] = acc[h];
    __syncthreads();

    for (int o = tid; o < 64*NH; o += 256) {
        const int rr = o / NH, h = o % NH;
        float sv = part[(rr*4+0)*NH + h] + part[(rr*4+1)*NH + h]
                 + part[(rr*4+2)*NH + h] + part[(rr*4+3)*NH + h];
        g_bpair[(size_t)(row0 + rr)*NH + h] = 0.5773502692f * (sv + bb[h]);
    }
}

// ---------------- Kernel 4: qk logits GEMM  Q'[h] @ K'^T[h] -----------------
// grid (jtile=4, itile=8, h=12), block 256. Out tile 64x128, K=32 single pass.
__global__ void qk_gemm(void)
{
    __shared__ float Qs[64][32];
    __shared__ float Ks[32][128];
    const int tid = threadIdx.x;
    const int j0 = blockIdx.x * 128;
    const int i0 = blockIdx.y * 64;
    const int h  = blockIdx.z;

    for (int idx = tid; idx < 2048; idx += 256) {
        const int r = idx >> 5, d = idx & 31;
        Qs[r][d] = g_qaug[((i0+r)*NH + h)*32 + d];
    }
    for (int idx = tid; idx < 4096; idx += 256) {
        const int d = idx >> 7, j = idx & 127;
        Ks[d][j] = g_kaugT[(h*32 + d)*NTOK + j0 + j];
    }
    __syncthreads();

    const int ty = tid >> 5, tx = tid & 31;
    const int r0 = ty * 8;
    float4 acc[8];
    #pragma unroll
    for (int rr = 0; rr < 8; rr++) acc[rr] = make_float4(0.f,0.f,0.f,0.f);

    #pragma unroll
    for (int d = 0; d < 32; d++) {
        const float4 k4 = *(const float4*)&Ks[d][tx*4];
        #pragma unroll
        for (int rr = 0; rr < 8; rr++) {
            const float qv = Qs[r0+rr][d];
            acc[rr].x += qv*k4.x; acc[rr].y += qv*k4.y;
            acc[rr].z += qv*k4.z; acc[rr].w += qv*k4.w;
        }
    }
    #pragma unroll
    for (int rr = 0; rr < 8; rr++)
        *(float4*)&g_qk[(size_t)(h*NTOK + i0+r0+rr)*NTOK + j0 + tx*4] = acc[rr];
}

// ---------------- Kernel 5: softmax over logits ------------------------------
// grid 512 (per i), block 512 (per j).
__global__ void softmax_kernel(const float* __restrict__ mask)
{
    __shared__ float lgm[NH][NTOK];
    __shared__ float sinv[NH];
    const int i = blockIdx.x;
    const int j = threadIdx.x;

    const float mterm = 100000.0f * (mask[i]*mask[j] - 1.0f);
    float bp[NH];
    {
        const float4* bpp = (const float4*)&g_bpair[(size_t)(i*NTOK + j)*NH];
        const float4 b0 = bpp[0], b1 = bpp[1], b2 = bpp[2];
        bp[0]=b0.x; bp[1]=b0.y; bp[2]=b0.z; bp[3]=b0.w;
        bp[4]=b1.x; bp[5]=b1.y; bp[6]=b1.z; bp[7]=b1.w;
        bp[8]=b2.x; bp[9]=b2.y; bp[10]=b2.z; bp[11]=b2.w;
    }
    #pragma unroll
    for (int h = 0; h < NH; h++)
        lgm[h][j] = g_qk[(size_t)(h*NTOK + i)*NTOK + j] + bp[h] + mterm;
    __syncthreads();

    const int lane = j & 31, wrp = j >> 5;
    if (wrp < NH) {
        float m = -3.0e38f;
        #pragma unroll
        for (int t = 0; t < 16; t++)
            m = fmaxf(m, lgm[wrp][t*32 + lane]);
        #pragma unroll
        for (int o = 16; o > 0; o >>= 1)
            m = fmaxf(m, __shfl_xor_sync(0xffffffffu, m, o));
        float su = 0.f;
        #pragma unroll
        for (int t = 0; t < 16; t++) {
            const float e = __expf(lgm[wrp][t*32 + lane] - m);
            lgm[wrp][t*32 + lane] = e;
            su += e;
        }
        #pragma unroll
        for (int o = 16; o > 0; o >>= 1)
            su += __shfl_xor_sync(0xffffffffu, su, o);
        if (lane == 0) sinv[wrp] = 1.0f / su;
    }
    __syncthreads();

    #pragma unroll
    for (int h = 0; h < NH; h++)
        g_attn[(size_t)(h*NTOK + i)*NTOK + j] = lgm[h][j] * sinv[h];
}

// ---------------- Kernel 6: o & o_pt GEMM + rotation epilogue ---------------
// grid (itile=16, h=12), block 256. Out tile 32x40, K=512 in chunks of 64.
__global__ void ovh_gemm(const float* __restrict__ rot, const float* __restrict__ trans)
{
    __shared__ float As[32][65];
    __shared__ float Vs[64][40];
    __shared__ float Cs[32][40];
    const int tid = threadIdx.x;
    const int i0 = blockIdx.x * 32;
    const int h  = blockIdx.y;

    const int r = tid & 31, g = tid >> 5;   // g in 0..7, 5 cols each
    float acc[5] = {0.f,0.f,0.f,0.f,0.f};

    for (int k0 = 0; k0 < NTOK; k0 += 64) {
        for (int idx = tid; idx < 32*64; idx += 256) {
            const int row = idx >> 6, k = idx & 63;
            As[row][k] = g_attn[(size_t)(h*NTOK + i0+row)*NTOK + k0 + k];
        }
        for (int idx = tid; idx < 64*40; idx += 256) {
            const int k = idx / 40, c = idx % 40;
            Vs[k][c] = g_vcat[(h*NTOK + k0 + k)*40 + c];
        }
        __syncthreads();
        #pragma unroll 8
        for (int k = 0; k < 64; k++) {
            const float a = As[r][k];
            #pragma unroll
            for (int u = 0; u < 5; u++)
                acc[u] += a * Vs[k][g*5 + u];
        }
        __syncthreads();
    }
    #pragma unroll
    for (int u = 0; u < 5; u++) Cs[r][g*5 + u] = acc[u];
    __syncthreads();

    // epilogue: o copy + o_pt inverse rotation + norm
    for (int idx = tid; idx < 32*16; idx += 256) {
        const int rr = idx >> 4, c = idx & 15;
        g_cat[(i0+rr)*NOUTD + h*16 + c] = Cs[rr][c];
    }
    for (int idx = tid; idx < 32*8; idx += 256) {
        const int rr = idx >> 3, p = idx & 7;
        const int i = i0 + rr;
        const float gx = Cs[rr][16 + p*3 + 0] - trans[i*3+0];
        const float gy = Cs[rr][16 + p*3 + 1] - trans[i*3+1];
        const float gz = Cs[rr][16 + p*3 + 2] - trans[i*3+2];
        const float* R = rot + i*9;
        const float lx = R[0]*gx + R[3]*gy + R[6]*gz;
        const float ly = R[1]*gx + R[4]*gy + R[7]*gz;
        const float lz = R[2]*gx + R[5]*gy + R[8]*gz;
        const int m = h*8 + p;
        g_cat[i*NOUTD + 192 + m] = lx;
        g_cat[i*NOUTD + 288 + m] = ly;
        g_cat[i*NOUTD + 384 + m] = lz;
        g_cat[i*NOUTD + 480 + m] = sqrtf(lx*lx + ly*ly + lz*lz + 1e-8f);
    }
}

// ---------------- Kernel 7: o_pair = a @ z ----------------------------------
// grid 512 (per i), block 512 (16 warps: 8 j-slices x 2 head-groups).
__global__ void __launch_bounds__(512, 4)
opair_kernel(const float* __restrict__ z)
{
    __shared__ float part[8][NH][128];   // 48KB
    const int i = blockIdx.x;
    const int tid = threadIdx.x;
    const int w = tid >> 5, l = tid & 31;
    const int jslice = w & 7;
    const int hb = (w >> 3) * 6;
    const int jbase = jslice * 64;

    // a values for this warp's slice, 2 j per lane, 6 heads
    float av0[6], av1[6];
    #pragma unroll
    for (int hh = 0; hh < 6; hh++) {
        av0[hh] = g_attn[(size_t)((hb+hh)*NTOK + i)*NTOK + jbase + l*2 + 0];
        av1[hh] = g_attn[(size_t)((hb+hh)*NTOK + i)*NTOK + jbase + l*2 + 1];
    }

    float4 acc[6];
    #pragma unroll
    for (int hh = 0; hh < 6; hh++) acc[hh] = make_float4(0.f,0.f,0.f,0.f);

    const float4* zq = (const float4*)(z + (size_t)(i*NTOK + jbase)*NCZ) + l;
    #pragma unroll 2
    for (int jj2 = 0; jj2 < 32; jj2++) {
        const float4 zv0 = zq[(jj2*2 + 0)*32];
        const float4 zv1 = zq[(jj2*2 + 1)*32];
        #pragma unroll
        for (int hh = 0; hh < 6; hh++) {
            const float a0 = __shfl_sync(0xffffffffu, av0[hh], jj2);
            acc[hh].x += a0*zv0.x; acc[hh].y += a0*zv0.y;
            acc[hh].z += a0*zv0.z; acc[hh].w += a0*zv0.w;
        }
        #pragma unroll
        for (int hh = 0; hh < 6; hh++) {
            const float a1 = __shfl_sync(0xffffffffu, av1[hh], jj2);
            acc[hh].x += a1*zv1.x; acc[hh].y += a1*zv1.y;
            acc[hh].z += a1*zv1.z; acc[hh].w += a1*zv1.w;
        }
    }
    #pragma unroll
    for (int hh = 0; hh < 6; hh++)
        *(float4*)&part[jslice][hb+hh][l*4] = acc[hh];
    __syncthreads();

    for (int o = tid; o < NH*128; o += 512) {
        const int h = o >> 7, c = o & 127;
        float sv = 0.f;
        #pragma unroll
        for (int sl = 0; sl < 8; sl++) sv += part[sl][h][c];
        g_cat[i*NOUTD + 576 + o] = sv;
    }
}

// ---------------- Kernel 8: final GEMM cat(512x2112) @ Wout(2112x384) -------
__global__ void final_gemm(const float* __restrict__ Wout, const float* __restrict__ bout,
                           float* __restrict__ out)
{
    __shared__ float As[32][36];
    __shared__ float Bs[32][36];
    const int bx = blockIdx.x, by = blockIdx.y;
    const int tid = threadIdx.x;
    const int tx = tid & 15, ty = tid >> 4;
    const int lr = tid >> 3, lc = (tid & 7)*4;
    float c00=0.f, c01=0.f, c10=0.f, c11=0.f;
    for (int kt = 0; kt < NOUTD; kt += 32) {
        *(float4*)&As[lr][lc] = *(const float4*)&g_cat[(by*32 + lr)*NOUTD + kt + lc];
        *(float4*)&Bs[lr][lc] = *(const float4*)&Wout[(kt + lr)*NCS + bx*32 + lc];
        __syncthreads();
        #pragma unroll
        for (int k = 0; k < 32; k++) {
            const float aa0 = As[ty*2+0][k], aa1 = As[ty*2+1][k];
            const float bb0 = Bs[k][tx*2+0], bb1 = Bs[k][tx*2+1];
            c00 += aa0*bb0; c01 += aa0*bb1; c10 += aa1*bb0; c11 += aa1*bb1;
        }
        __syncthreads();
    }
    const int row = by*32 + ty*2, col = bx*32 + tx*2;
    out[row*NCS + col]         = c00 + bout[col];
    out[row*NCS + col+1]       = c01 + bout[col+1];
    out[(row+1)*NCS + col]     = c10 + bout[col];
    out[(row+1)*NCS + col+1]   = c11 + bout[col+1];
}

// ---------------- launch ------------------------------------------------------
extern "C" void kernel_launch(void* const* d_in, const int* in_sizes, int n_in,
                              void* d_out, int out_size)
{
    const float* s     = (const float*)d_in[0];
    const float* z     = (const float*)d_in[1];
    const float* rot   = (const float*)d_in[2];
    const float* trans = (const float*)d_in[3];
    const float* mask  = (const float*)d_in[4];
    const float* Wq    = (const float*)d_in[5];
    const float* bq    = (const float*)d_in[6];
    const float* Wkv   = (const float*)d_in[7];
    const float* bkv   = (const float*)d_in[8];
    const float* Wqp   = (const float*)d_in[9];
    const float* bqp   = (const float*)d_in[10];
    const float* Wkvp  = (const float*)d_in[11];
    const float* bkvp  = (const float*)d_in[12];
    const float* Wb    = (const float*)d_in[13];
    const float* bb    = (const float*)d_in[14];
    const float* hwts  = (const float*)d_in[15];
    const float* Wout  = (const float*)d_in[16];
    const float* bout  = (const float*)d_in[17];
    float* out = (float*)d_out;

    proj_kernel<<<dim3(32,19,1), 256>>>(s, Wq,bq, Wkv,bkv, Wqp,bqp, Wkvp,bkvp);
    prep_kernel<<<NTOK, 256>>>(rot, trans, hwts);
    bpair_kernel<<<4096, 256>>>(z, Wb, bb);
    qk_gemm<<<dim3(4,8,12), 256>>>();
    softmax_kernel<<<NTOK, 512>>>(mask);
    ovh_gemm<<<dim3(16,12,1), 256>>>(rot, trans);
    opair_kernel<<<NTOK, 512>>>(z);
    final_gemm<<<dim3(12,16,1), 256>>>(Wout, bout, out);
}

// round 4
// speedup vs baseline: 1.5033x; 1.5033x over previous
#include <cuda_runtime.h>
#include <math.h>

#define NTOK 512
#define NH   12
#define NCH  16
#define NPQ  4
#define NPV  8
#define NCS  384
#define NCZ  128
#define NHC  192
#define NOUTD 2112
#define NNN  (NTOK*NTOK)

// ---------------- scratch ----------------------------------------------------
__device__ float g_qraw[NTOK*NHC];
__device__ float g_kvraw[NTOK*2*NHC];
__device__ float g_qpraw[NTOK*NH*NPQ*3];
__device__ float g_kvpraw[NTOK*NH*(NPQ+NPV)*3];
__device__ float g_qaug[NTOK*NH*32];             // augmented Q' [i][h][32]
__device__ float g_kaugT[NH*32*NTOK];            // augmented K'^T [h][d][j]
__device__ float g_vcat[NH*NTOK*40];             // [h][j][40]
__device__ float g_bpairT[NH*NNN];               // 0.577*(z@Wb+bb) [h][i][j]
__device__ float g_qk[NH*NNN];                   // [h][i][j]
__device__ float g_attn[NH*NNN];                 // [h][i][j]
__device__ float g_cat[NTOK*NOUTD];
__device__ float g_fpart[2*NTOK*NCS];

// ---------------- Kernel 1: projections from s ------------------------------
__global__ void proj_kernel(const float* __restrict__ s,
                            const float* __restrict__ Wq,   const float* __restrict__ bq,
                            const float* __restrict__ Wkv,  const float* __restrict__ bkv,
                            const float* __restrict__ Wqp,  const float* __restrict__ bqp,
                            const float* __restrict__ Wkvp, const float* __restrict__ bkvp)
{
    __shared__ float s_s[16][384];
    const int tid = threadIdx.x;
    const int i0  = blockIdx.x * 16;
    for (int idx = tid; idx < 16*384; idx += 256)
        s_s[idx/384][idx%384] = s[i0*384 + idx];
    __syncthreads();

    const float* W; const float* bias; float* out; int Nc; int ct;
    const int by = blockIdx.y;
    if      (by < 3)  { W=Wq;   bias=bq;   out=g_qraw;   Nc=192; ct=by;    }
    else if (by < 9)  { W=Wkv;  bias=bkv;  out=g_kvraw;  Nc=384; ct=by-3;  }
    else if (by < 12) { W=Wqp;  bias=bqp;  out=g_qpraw;  Nc=144; ct=by-9;  }
    else              { W=Wkvp; bias=bkvp; out=g_kvpraw; Nc=432; ct=by-12; }

    const int col = ct*64 + (tid & 63);
    if (col >= Nc) return;
    const int t0 = (tid >> 6) * 4;

    float a0=0.f, a1=0.f, a2=0.f, a3=0.f;
    #pragma unroll 4
    for (int k = 0; k < 384; k += 4) {
        float w0 = W[(k+0)*Nc + col];
        float w1 = W[(k+1)*Nc + col];
        float w2 = W[(k+2)*Nc + col];
        float w3 = W[(k+3)*Nc + col];
        float4 v;
        v = *(const float4*)&s_s[t0+0][k]; a0 += v.x*w0 + v.y*w1 + v.z*w2 + v.w*w3;
        v = *(const float4*)&s_s[t0+1][k]; a1 += v.x*w0 + v.y*w1 + v.z*w2 + v.w*w3;
        v = *(const float4*)&s_s[t0+2][k]; a2 += v.x*w0 + v.y*w1 + v.z*w2 + v.w*w3;
        v = *(const float4*)&s_s[t0+3][k]; a3 += v.x*w0 + v.y*w1 + v.z*w2 + v.w*w3;
    }
    const float bv = bias[col];
    out[(i0+t0+0)*Nc + col] = a0 + bv;
    out[(i0+t0+1)*Nc + col] = a1 + bv;
    out[(i0+t0+2)*Nc + col] = a2 + bv;
    out[(i0+t0+3)*Nc + col] = a3 + bv;
}

// ---------------- Kernel 2: rotate points, build Q'/K'^T/Vcat ---------------
__global__ void prep_kernel(const float* __restrict__ rot, const float* __restrict__ trans,
                            const float* __restrict__ hwts)
{
    __shared__ float qpts_s[144];
    __shared__ float kpts_s[144];
    __shared__ float vpts_s[288];
    __shared__ float shw[NH];
    const int i = blockIdx.x;
    const int tid = threadIdx.x;

    if (tid < NH)
        shw[tid] = log1pf(__expf(hwts[tid])) * 0.1360827635f;

    if (tid < 192) {
        const int m = tid;
        const float* R = rot + i*9;
        const float tx = trans[i*3+0], ty = trans[i*3+1], tz = trans[i*3+2];
        float x, y, zc; float* dst;
        if (m < 48) {
            const float* src = g_qpraw + i*144;
            x = src[m]; y = src[48+m]; zc = src[96+m];
            dst = qpts_s + m*3;
        } else {
            const int mm = m - 48;
            const float* src = g_kvpraw + i*432;
            x = src[mm]; y = src[144+mm]; zc = src[288+mm];
            const int h = mm / 12, pp = mm % 12;
            if (pp < 4) dst = kpts_s + (h*4+pp)*3;
            else        dst = vpts_s + (h*8 + pp-4)*3;
        }
        dst[0] = R[0]*x + R[1]*y + R[2]*zc + tx;
        dst[1] = R[3]*x + R[4]*y + R[5]*zc + ty;
        dst[2] = R[6]*x + R[7]*y + R[8]*zc + tz;
    }
    __syncthreads();

    for (int idx = tid; idx < 384; idx += 256) {
        const int h = idx >> 5, d = idx & 31;
        const float hw = shw[h];
        float qv, kv;
        if (d < 16) {
            qv = 0.1443375673f * g_qraw[i*NHC + h*16 + d];
            kv = g_kvraw[i*384 + h*32 + d];
        } else if (d < 28) {
            qv = hw * qpts_s[h*12 + d-16];
            kv = kpts_s[h*12 + d-16];
        } else if (d == 28) {
            float qn = 0.f;
            #pragma unroll
            for (int e = 0; e < 12; e++) { const float t = qpts_s[h*12+e]; qn += t*t; }
            qv = -0.5f * hw * qn;
            kv = 1.0f;
        } else if (d == 29) {
            qv = 1.0f;
            float kn = 0.f;
            #pragma unroll
            for (int e = 0; e < 12; e++) { const float t = kpts_s[h*12+e]; kn += t*t; }
            kv = -0.5f * hw * kn;
        } else { qv = 0.f; kv = 0.f; }
        g_qaug[(i*NH + h)*32 + d] = qv;
        g_kaugT[(h*32 + d)*NTOK + i] = kv;
    }

    for (int idx = tid; idx < 480; idx += 256) {
        const int h = idx / 40, d = idx % 40;
        const float v = (d < 16) ? g_kvraw[i*384 + h*32 + 16 + d]
                                 : vpts_s[h*24 + d-16];
        g_vcat[(h*NTOK + i)*40 + d] = v;
    }
}

// ---------------- Kernel 3: bpairT = 0.577*(z@Wb + bb), streaming -----------
// grid 4096 (64 global rows each), block 256.
__global__ void __launch_bounds__(256, 6)
bpair_kernel(const float* __restrict__ z, const float* __restrict__ Wb,
             const float* __restrict__ bb)
{
    __shared__ float wbT[NH][128];
    __shared__ float tr[64][NH];
    const int tid = threadIdx.x;
    const int row0 = blockIdx.x * 64;
    const int i  = row0 >> 9;
    const int j0 = row0 & 511;

    for (int idx = tid; idx < NH*128; idx += 256) {
        const int h = idx >> 7, c = idx & 127;
        wbT[h][c] = Wb[c*NH + h];
    }
    __syncthreads();

    const int r = tid >> 2, q = tid & 3;
    const float4* zp = (const float4*)z + (size_t)(row0 + r)*32;

    float4 zv[8];
    #pragma unroll
    for (int it = 0; it < 8; it++) zv[it] = zp[it*4 + q];

    float acc[NH];
    #pragma unroll
    for (int h = 0; h < NH; h++) acc[h] = 0.f;

    #pragma unroll
    for (int it = 0; it < 8; it++) {
        const int cbase = (it*4 + q) * 4;
        #pragma unroll
        for (int h = 0; h < NH; h++) {
            const float4 wv = *(const float4*)&wbT[h][cbase];
            acc[h] += zv[it].x*wv.x + zv[it].y*wv.y + zv[it].z*wv.z + zv[it].w*wv.w;
        }
    }
    // quad reduction (lanes 4r..4r+3 share row r)
    #pragma unroll
    for (int h = 0; h < NH; h++) {
        acc[h] += __shfl_xor_sync(0xffffffffu, acc[h], 1);
        acc[h] += __shfl_xor_sync(0xffffffffu, acc[h], 2);
    }
    if (q == 0) {
        #pragma unroll
        for (int h = 0; h < NH; h++) tr[r][h] = acc[h];
    }
    __syncthreads();

    for (int o = tid; o < 64*NH; o += 256) {
        const int h = o >> 6, jj = o & 63;
        g_bpairT[(size_t)h*NNN + i*NTOK + j0 + jj] = 0.5773502692f * (tr[jj][h] + bb[h]);
    }
}

// ---------------- Kernel 4: qk GEMM  Q'[h] @ K'^T[h], 64x64 tiles -----------
__global__ void qk_gemm(void)
{
    __shared__ float Qs[64][33];
    __shared__ float Ks[32][68];
    const int tid = threadIdx.x;
    const int j0 = blockIdx.x * 64;
    const int i0 = blockIdx.y * 64;
    const int h  = blockIdx.z;

    for (int idx = tid; idx < 2048; idx += 256) {
        const int r = idx >> 5, d = idx & 31;
        Qs[r][d] = g_qaug[((i0+r)*NH + h)*32 + d];
    }
    for (int idx = tid; idx < 2048; idx += 256) {
        const int d = idx >> 6, j = idx & 63;
        Ks[d][j] = g_kaugT[(h*32 + d)*NTOK + j0 + j];
    }
    __syncthreads();

    const int ty = tid >> 4, tx = tid & 15;
    float4 acc[4];
    #pragma unroll
    for (int rr = 0; rr < 4; rr++) acc[rr] = make_float4(0.f,0.f,0.f,0.f);

    #pragma unroll
    for (int d = 0; d < 32; d++) {
        const float4 k4 = *(const float4*)&Ks[d][tx*4];
        #pragma unroll
        for (int rr = 0; rr < 4; rr++) {
            const float qv = Qs[ty*4+rr][d];
            acc[rr].x += qv*k4.x; acc[rr].y += qv*k4.y;
            acc[rr].z += qv*k4.z; acc[rr].w += qv*k4.w;
        }
    }
    #pragma unroll
    for (int rr = 0; rr < 4; rr++)
        *(float4*)&g_qk[(size_t)(h*NTOK + i0 + ty*4+rr)*NTOK + j0 + tx*4] = acc[rr];
}

// ---------------- Kernel 5: softmax -----------------------------------------
__global__ void softmax_kernel(const float* __restrict__ mask)
{
    __shared__ float lgm[NH][NTOK];
    __shared__ float sinv[NH];
    const int i = blockIdx.x;
    const int j = threadIdx.x;

    const float mterm = 100000.0f * (mask[i]*mask[j] - 1.0f);
    #pragma unroll
    for (int h = 0; h < NH; h++)
        lgm[h][j] = g_qk[(size_t)h*NNN + i*NTOK + j]
                  + g_bpairT[(size_t)h*NNN + i*NTOK + j] + mterm;
    __syncthreads();

    const int lane = j & 31, wrp = j >> 5;
    if (wrp < NH) {
        float m = -3.0e38f;
        #pragma unroll
        for (int t = 0; t < 16; t++)
            m = fmaxf(m, lgm[wrp][t*32 + lane]);
        #pragma unroll
        for (int o = 16; o > 0; o >>= 1)
            m = fmaxf(m, __shfl_xor_sync(0xffffffffu, m, o));
        float su = 0.f;
        #pragma unroll
        for (int t = 0; t < 16; t++) {
            const float e = __expf(lgm[wrp][t*32 + lane] - m);
            lgm[wrp][t*32 + lane] = e;
            su += e;
        }
        #pragma unroll
        for (int o = 16; o > 0; o >>= 1)
            su += __shfl_xor_sync(0xffffffffu, su, o);
        if (lane == 0) sinv[wrp] = 1.0f / su;
    }
    __syncthreads();

    #pragma unroll
    for (int h = 0; h < NH; h++)
        g_attn[(size_t)h*NNN + i*NTOK + j] = lgm[h][j] * sinv[h];
}

// ---------------- Kernel 6: o & o_pt GEMM + rotation epilogue ---------------
__global__ void ovh_gemm(const float* __restrict__ rot, const float* __restrict__ trans)
{
    __shared__ float As[32][65];
    __shared__ float Vs[64][40];
    __shared__ float Cs[32][40];
    const int tid = threadIdx.x;
    const int i0 = blockIdx.x * 32;
    const int h  = blockIdx.y;

    const int r = tid & 31, g = tid >> 5;
    float acc[5] = {0.f,0.f,0.f,0.f,0.f};

    for (int k0 = 0; k0 < NTOK; k0 += 64) {
        for (int idx = tid; idx < 32*64; idx += 256) {
            const int row = idx >> 6, k = idx & 63;
            As[row][k] = g_attn[(size_t)(h*NTOK + i0+row)*NTOK + k0 + k];
        }
        for (int idx = tid; idx < 64*40; idx += 256) {
            const int k = idx / 40, c = idx % 40;
            Vs[k][c] = g_vcat[(h*NTOK + k0 + k)*40 + c];
        }
        __syncthreads();
        #pragma unroll 8
        for (int k = 0; k < 64; k++) {
            const float a = As[r][k];
            #pragma unroll
            for (int u = 0; u < 5; u++)
                acc[u] += a * Vs[k][g*5 + u];
        }
        __syncthreads();
    }
    #pragma unroll
    for (int u = 0; u < 5; u++) Cs[r][g*5 + u] = acc[u];
    __syncthreads();

    for (int idx = tid; idx < 32*16; idx += 256) {
        const int rr = idx >> 4, c = idx & 15;
        g_cat[(i0+rr)*NOUTD + h*16 + c] = Cs[rr][c];
    }
    for (int idx = tid; idx < 32*8; idx += 256) {
        const int rr = idx >> 3, p = idx & 7;
        const int i = i0 + rr;
        const float gx = Cs[rr][16 + p*3 + 0] - trans[i*3+0];
        const float gy = Cs[rr][16 + p*3 + 1] - trans[i*3+1];
        const float gz = Cs[rr][16 + p*3 + 2] - trans[i*3+2];
        const float* R = rot + i*9;
        const float lx = R[0]*gx + R[3]*gy + R[6]*gz;
        const float ly = R[1]*gx + R[4]*gy + R[7]*gz;
        const float lz = R[2]*gx + R[5]*gy + R[8]*gz;
        const int m = h*8 + p;
        g_cat[i*NOUTD + 192 + m] = lx;
        g_cat[i*NOUTD + 288 + m] = ly;
        g_cat[i*NOUTD + 384 + m] = lz;
        g_cat[i*NOUTD + 480 + m] = sqrtf(lx*lx + ly*ly + lz*lz + 1e-8f);
    }
}

// ---------------- Kernel 7: o_pair = a @ z  (no shuffles) -------------------
// grid 512 (per i), block 256 = 8 warps; warp w owns j in [w*64, w*64+64),
// all 12 heads; lane l owns z columns 4l..4l+3.
__global__ void __launch_bounds__(256, 3)
opair_kernel(const float* __restrict__ z)
{
    __shared__ float a_s[NH][NTOK];        // 24 KB
    __shared__ float part[4][NH][128];     // 24 KB
    const int i = blockIdx.x;
    const int tid = threadIdx.x;
    const int w = tid >> 5, l = tid & 31;
    const int jbase = w * 64;

    for (int idx = tid; idx < NH*NTOK; idx += 256)
        a_s[idx >> 9][idx & 511] = g_attn[(size_t)(idx >> 9)*NNN + i*NTOK + (idx & 511)];
    __syncthreads();

    float4 acc[NH];
    #pragma unroll
    for (int h = 0; h < NH; h++) acc[h] = make_float4(0.f,0.f,0.f,0.f);

    const float4* zq = (const float4*)(z + ((size_t)i*NTOK + jbase)*NCZ) + l;
    for (int jj4 = 0; jj4 < 16; jj4++) {
        const float4 zv0 = zq[(jj4*4 + 0)*32];
        const float4 zv1 = zq[(jj4*4 + 1)*32];
        const float4 zv2 = zq[(jj4*4 + 2)*32];
        const float4 zv3 = zq[(jj4*4 + 3)*32];
        #pragma unroll
        for (int h = 0; h < NH; h++) {
            const float4 a4 = *(const float4*)&a_s[h][jbase + jj4*4];
            acc[h].x += a4.x*zv0.x + a4.y*zv1.x + a4.z*zv2.x + a4.w*zv3.x;
            acc[h].y += a4.x*zv0.y + a4.y*zv1.y + a4.z*zv2.y + a4.w*zv3.y;
            acc[h].z += a4.x*zv0.z + a4.y*zv1.z + a4.z*zv2.z + a4.w*zv3.z;
            acc[h].w += a4.x*zv0.w + a4.y*zv1.w + a4.z*zv2.w + a4.w*zv3.w;
        }
    }

    if (w < 4) {
        #pragma unroll
        for (int h = 0; h < NH; h++)
            *(float4*)&part[w][h][l*4] = acc[h];
    }
    __syncthreads();
    if (w >= 4) {
        #pragma unroll
        for (int h = 0; h < NH; h++) {
            float4 p = *(const float4*)&part[w-4][h][l*4];
            p.x += acc[h].x; p.y += acc[h].y; p.z += acc[h].z; p.w += acc[h].w;
            *(float4*)&part[w-4][h][l*4] = p;
        }
    }
    __syncthreads();

    for (int o = tid; o < NH*128; o += 256) {
        const int h = o >> 7, c = o & 127;
        g_cat[i*NOUTD + 576 + o] =
            part[0][h][c] + part[1][h][c] + part[2][h][c] + part[3][h][c];
    }
}

// ---------------- Kernel 8: final GEMM, K-split 2 ----------------------------
__global__ void final_gemm(const float* __restrict__ Wout)
{
    __shared__ float As[32][36];
    __shared__ float Bs[32][36];
    const int bx = blockIdx.x, by = blockIdx.y, bz = blockIdx.z;
    const int tid = threadIdx.x;
    const int tx = tid & 15, ty = tid >> 4;
    const int lr = tid >> 3, lc = (tid & 7)*4;
    const int kbeg = bz * 1056;
    float c00=0.f, c01=0.f, c10=0.f, c11=0.f;
    for (int kt = kbeg; kt < kbeg + 1056; kt += 32) {
        *(float4*)&As[lr][lc] = *(const float4*)&g_cat[(by*32 + lr)*NOUTD + kt + lc];
        *(float4*)&Bs[lr][lc] = *(const float4*)&Wout[(kt + lr)*NCS + bx*32 + lc];
        __syncthreads();
        #pragma unroll
        for (int k = 0; k < 32; k++) {
            const float aa0 = As[ty*2+0][k], aa1 = As[ty*2+1][k];
            const float bb0 = Bs[k][tx*2+0], bb1 = Bs[k][tx*2+1];
            c00 += aa0*bb0; c01 += aa0*bb1; c10 += aa1*bb0; c11 += aa1*bb1;
        }
        __syncthreads();
    }
    const int row = by*32 + ty*2, col = bx*32 + tx*2;
    float* dst = g_fpart + (size_t)bz*NTOK*NCS;
    dst[row*NCS + col]       = c00;
    dst[row*NCS + col+1]     = c01;
    dst[(row+1)*NCS + col]   = c10;
    dst[(row+1)*NCS + col+1] = c11;
}

__global__ void final_add(const float* __restrict__ bout, float* __restrict__ out)
{
    const int o = blockIdx.x*256 + threadIdx.x;
    if (o >= NTOK*NCS) return;
    out[o] = g_fpart[o] + g_fpart[NTOK*NCS + o] + bout[o % NCS];
}

// ---------------- launch ------------------------------------------------------
extern "C" void kernel_launch(void* const* d_in, const int* in_sizes, int n_in,
                              void* d_out, int out_size)
{
    const float* s     = (const float*)d_in[0];
    const float* z     = (const float*)d_in[1];
    const float* rot   = (const float*)d_in[2];
    const float* trans = (const float*)d_in[3];
    const float* mask  = (const float*)d_in[4];
    const float* Wq    = (const float*)d_in[5];
    const float* bq    = (const float*)d_in[6];
    const float* Wkv   = (const float*)d_in[7];
    const float* bkv   = (const float*)d_in[8];
    const float* Wqp   = (const float*)d_in[9];
    const float* bqp   = (const float*)d_in[10];
    const float* Wkvp  = (const float*)d_in[11];
    const float* bkvp  = (const float*)d_in[12];
    const float* Wb    = (const float*)d_in[13];
    const float* bb    = (const float*)d_in[14];
    const float* hwts  = (const float*)d_in[15];
    const float* Wout  = (const float*)d_in[16];
    const float* bout  = (const float*)d_in[17];
    float* out = (float*)d_out;

    proj_kernel<<<dim3(32,19,1), 256>>>(s, Wq,bq, Wkv,bkv, Wqp,bqp, Wkvp,bkvp);
    prep_kernel<<<NTOK, 256>>>(rot, trans, hwts);
    bpair_kernel<<<4096, 256>>>(z, Wb, bb);
    qk_gemm<<<dim3(8,8,12), 256>>>();
    softmax_kernel<<<NTOK, 512>>>(mask);
    ovh_gemm<<<dim3(16,12,1), 256>>>(rot, trans);
    opair_kernel<<<NTOK, 256>>>(z);
    final_gemm<<<dim3(12,16,2), 256>>>(Wout);
    final_add<<<(NTOK*NCS + 255)/256, 256>>>(bout, out);
}